// round 3
// baseline (speedup 1.0000x reference)
#include <cuda_runtime.h>
#include <cuda_bf16.h>
#include <math.h>

#define QL 2048
#define BSZ 2
#define NH 12
#define DH 64
#define DM 768
#define NBH (BSZ*NH)   // 24
#define NEG_INF (-1e30f)

// ---------------- static scratch (no runtime allocation allowed) ----------------
__device__ float g_Q[(size_t)NBH*QL*DH];      // [b*NH+n][i][d]
__device__ float g_K[(size_t)NBH*QL*DH];
__device__ float g_V[(size_t)NBH*QL*DH];
__device__ float g_ck[NBH*QL];                // rwb_n . k_j
__device__ float g_S[(size_t)NBH*QL*QL];      // scores / probs (402 MB)
__device__ float g_AV[(size_t)QL*BSZ*DM];     // attn_vec  [ib][h]
__device__ float g_AO[(size_t)QL*BSZ*DM];     // attn_out  [ib][m]

// ---------------- Kernel 1: QKV projection GEMM ----------------
// C[ib][h] = sum_m w[ib][m] * qkv_w[h][m];  ib in [0,4096), h in [0,2304)
__global__ __launch_bounds__(256) void qkv_gemm(const float* __restrict__ A,
                                                const float* __restrict__ W) {
    __shared__ float As[128][17];
    __shared__ float Bs[128][17];
    const int i0 = blockIdx.y * 128;
    const int j0 = blockIdx.x * 128;
    const int tid = threadIdx.x;
    const int tx = tid & 15, ty = tid >> 4;

    float acc[8][8];
    #pragma unroll
    for (int a = 0; a < 8; a++)
        #pragma unroll
        for (int c = 0; c < 8; c++) acc[a][c] = 0.f;

    for (int kk = 0; kk < DM; kk += 16) {
        #pragma unroll
        for (int x = tid; x < 512; x += 256) {
            int r = x >> 2, c4 = (x & 3) << 2;
            float4 av = *reinterpret_cast<const float4*>(&A[(size_t)(i0 + r) * DM + kk + c4]);
            As[r][c4 + 0] = av.x; As[r][c4 + 1] = av.y;
            As[r][c4 + 2] = av.z; As[r][c4 + 3] = av.w;
            float4 bv = *reinterpret_cast<const float4*>(&W[(size_t)(j0 + r) * DM + kk + c4]);
            Bs[r][c4 + 0] = bv.x; Bs[r][c4 + 1] = bv.y;
            Bs[r][c4 + 2] = bv.z; Bs[r][c4 + 3] = bv.w;
        }
        __syncthreads();
        #pragma unroll
        for (int k = 0; k < 16; k++) {
            float av[8], bv[8];
            #pragma unroll
            for (int a = 0; a < 8; a++) av[a] = As[ty + 16 * a][k];
            #pragma unroll
            for (int c = 0; c < 8; c++) bv[c] = Bs[tx + 16 * c][k];
            #pragma unroll
            for (int a = 0; a < 8; a++)
                #pragma unroll
                for (int c = 0; c < 8; c++) acc[a][c] += av[a] * bv[c];
        }
        __syncthreads();
    }

    #pragma unroll
    for (int a = 0; a < 8; a++) {
        int ib = i0 + ty + 16 * a;
        int i = ib >> 1, b = ib & 1;
        #pragma unroll
        for (int c = 0; c < 8; c++) {
            int h = j0 + tx + 16 * c;
            int which = h / DM;
            int hr = h - which * DM;
            int n = hr >> 6, dd = hr & 63;
            float* dst = (which == 0) ? g_Q : ((which == 1) ? g_K : g_V);
            dst[((size_t)(b * NH + n) * QL + i) * DH + dd] = acc[a][c];
        }
    }
}

// ---------------- Kernel 2: ck[bn][j] = r_w_bias[n] . K[bn][j] ----------------
__global__ __launch_bounds__(256) void ck_kernel(const float* __restrict__ rwb) {
    int idx = blockIdx.x * 256 + threadIdx.x;
    if (idx >= NBH * QL) return;
    int bn = idx / QL;
    int n = bn % NH;
    const float4* krow = reinterpret_cast<const float4*>(&g_K[(size_t)idx * DH]);
    const float4* wv = reinterpret_cast<const float4*>(&rwb[n * DH]);
    float s = 0.f;
    #pragma unroll
    for (int d = 0; d < DH / 4; d++) {
        float4 kv = krow[d], wvv = wv[d];
        s += kv.x * wvv.x + kv.y * wvv.y + kv.z * wvv.z + kv.w * wvv.w;
    }
    g_ck[idx] = s;
}

// ---------------- Kernel 3: fused causal score ----------------
// S[i][j] = (q_i.k_j + q_i.rr[i-j] + ck[j] + rb2[i-j]) * SCALE   for j<=i
// rr[d] = r_emb[QL-1-d][n],  rb2[d] = r_bias[QL-1-d][n]
// 64x64 tile, 256 threads, 4x4 microtile; 127-row rel band in smem.
// Rel-band loads grouped by diff = a-c (7 LDS/k-step instead of 16).
#define SC_SMEM_FLOATS (64*65 + 64*65 + 127*65 + 128 + 64)
__global__ __launch_bounds__(256) void score_kernel(const float* __restrict__ r_emb,
                                                    const float* __restrict__ r_bias) {
    int jt = blockIdx.x, it = blockIdx.y, bn = blockIdx.z;
    if (jt > it) return;
    extern __shared__ float sm[];
    float* Qs = sm;                 // 64*65
    float* Ks = Qs + 64 * 65;       // 64*65
    float* Rs = Ks + 64 * 65;       // 127*65
    float* Rb = Rs + 127 * 65;      // 128
    float* ckv = Rb + 128;          // 64

    const int n = bn % NH;
    const int i0 = it * 64, j0 = jt * 64;
    const int dmin = i0 - j0 - 63;
    const int tid = threadIdx.x;

    const float* Qg = g_Q + (size_t)bn * QL * DH;
    const float* Kg = g_K + (size_t)bn * QL * DH;

    #pragma unroll
    for (int x = tid; x < 1024; x += 256) {
        int r = x >> 4, c4 = (x & 15) << 2;
        float4 qv = *reinterpret_cast<const float4*>(&Qg[(size_t)(i0 + r) * DH + c4]);
        Qs[r * 65 + c4 + 0] = qv.x; Qs[r * 65 + c4 + 1] = qv.y;
        Qs[r * 65 + c4 + 2] = qv.z; Qs[r * 65 + c4 + 3] = qv.w;
        float4 kv = *reinterpret_cast<const float4*>(&Kg[(size_t)(j0 + r) * DH + c4]);
        Ks[r * 65 + c4 + 0] = kv.x; Ks[r * 65 + c4 + 1] = kv.y;
        Ks[r * 65 + c4 + 2] = kv.z; Ks[r * 65 + c4 + 3] = kv.w;
    }
    for (int x = tid; x < 2032; x += 256) {
        int r = x >> 4, c4 = (x & 15) << 2;
        int d = dmin + r;
        float4 rv = make_float4(0.f, 0.f, 0.f, 0.f);
        if (d >= 0)
            rv = *reinterpret_cast<const float4*>(
                &r_emb[(size_t)(QL - 1 - d) * (NH * DH) + n * DH + c4]);
        Rs[r * 65 + c4 + 0] = rv.x; Rs[r * 65 + c4 + 1] = rv.y;
        Rs[r * 65 + c4 + 2] = rv.z; Rs[r * 65 + c4 + 3] = rv.w;
    }
    if (tid < 127) {
        int d = dmin + tid;
        Rb[tid] = (d >= 0) ? r_bias[(QL - 1 - d) * NH + n] : 0.f;
    }
    if (tid < 64) ckv[tid] = g_ck[bn * QL + j0 + tid];
    __syncthreads();

    const int tx = tid & 15, ty = tid >> 4;
    // Rel row for cell (a,c): 63 + (ty-tx) + 16*(a-c). Group by g = (a-c)+3 in [0,7).
    const int rbase = (63 + ty - tx - 3 * 16) * 65;   // row for g=0, times pitch

    float acc[4][4];
    #pragma unroll
    for (int a = 0; a < 4; a++)
        #pragma unroll
        for (int c = 0; c < 4; c++) acc[a][c] = 0.f;

    #pragma unroll 4
    for (int k = 0; k < 64; k++) {
        float qv[4], kv[4], rv[7];
        #pragma unroll
        for (int a = 0; a < 4; a++) qv[a] = Qs[(ty + 16 * a) * 65 + k];
        #pragma unroll
        for (int c = 0; c < 4; c++) kv[c] = Ks[(tx + 16 * c) * 65 + k];
        #pragma unroll
        for (int g = 0; g < 7; g++) rv[g] = Rs[rbase + g * (16 * 65) + k];
        #pragma unroll
        for (int a = 0; a < 4; a++)
            #pragma unroll
            for (int c = 0; c < 4; c++)
                acc[a][c] += qv[a] * (kv[c] + rv[a - c + 3]);
    }

    float* Srow = g_S + (size_t)bn * QL * QL;
    #pragma unroll
    for (int a = 0; a < 4; a++) {
        int i = i0 + ty + 16 * a;
        #pragma unroll
        for (int c = 0; c < 4; c++) {
            int j = j0 + tx + 16 * c;
            float s;
            if (j > i) {
                s = NEG_INF;
            } else {
                s = (acc[a][c] + ckv[tx + 16 * c] + Rb[63 + ty + 16 * a - tx - 16 * c]) * 0.125f;
            }
            Srow[(size_t)i * QL + j] = s;
        }
    }
}

// ---------------- Kernel 4: causal row softmax (4-warp block, shuffle reduce) ----------------
__global__ __launch_bounds__(128) void softmax_kernel() {
    const int i = blockIdx.x, bn = blockIdx.y;
    float* row = g_S + (size_t)bn * QL * QL + (size_t)i * QL;
    const int len = i + 1;
    const int tid = threadIdx.x;
    const int lane = tid & 31, wrp = tid >> 5;
    __shared__ float red[4];

    float v[16];
    int cnt = 0;
    float m = NEG_INF;
    for (int j = tid; j < len; j += 128) { v[cnt] = row[j]; m = fmaxf(m, v[cnt]); cnt++; }
    #pragma unroll
    for (int s = 16; s > 0; s >>= 1) m = fmaxf(m, __shfl_xor_sync(0xffffffffu, m, s));
    if (lane == 0) red[wrp] = m;
    __syncthreads();
    m = fmaxf(fmaxf(red[0], red[1]), fmaxf(red[2], red[3]));

    float sum = 0.f;
    for (int x = 0; x < cnt; x++) { v[x] = __expf(v[x] - m); sum += v[x]; }
    #pragma unroll
    for (int s = 16; s > 0; s >>= 1) sum += __shfl_xor_sync(0xffffffffu, sum, s);
    __syncthreads();
    if (lane == 0) red[wrp] = sum;
    __syncthreads();
    const float inv = 1.f / (red[0] + red[1] + red[2] + red[3]);

    cnt = 0;
    for (int j = tid; j < len; j += 128) row[j] = v[cnt++] * inv;
    // zero tail up to this row's 128-aligned PV block boundary
    int jend = ((i >> 7) + 1) << 7;
    if (jend > QL) jend = QL;
    for (int j = len + tid; j < jend; j += 128) row[j] = 0.f;
}

// ---------------- Kernel 5: PV GEMM (causal-skipped) ----------------
// AV[i][b][n*64+d] = sum_j P[i][j] * V[j][d];  BM=128, BK=32, 8x4 microtile
__global__ __launch_bounds__(256) void pv_kernel() {
    __shared__ float Ps[128 * 33];
    __shared__ float Vs[32 * 64];
    const int iblk = blockIdx.x, bn = blockIdx.y;
    const int i0 = iblk * 128;
    const float* Pm = g_S + (size_t)bn * QL * QL;
    const float* Vg = g_V + (size_t)bn * QL * DH;
    const int tid = threadIdx.x, tx = tid & 15, ty = tid >> 4;

    float acc[8][4];
    #pragma unroll
    for (int a = 0; a < 8; a++)
        #pragma unroll
        for (int c = 0; c < 4; c++) acc[a][c] = 0.f;

    const int jlim = (i0 + 128 < QL) ? (i0 + 128) : QL;
    for (int j0 = 0; j0 < jlim; j0 += 32) {
        #pragma unroll
        for (int x = tid; x < 1024; x += 256) {
            int r = x >> 3, c4 = (x & 7) << 2;
            float4 pv = *reinterpret_cast<const float4*>(&Pm[(size_t)(i0 + r) * QL + j0 + c4]);
            Ps[r * 33 + c4 + 0] = pv.x; Ps[r * 33 + c4 + 1] = pv.y;
            Ps[r * 33 + c4 + 2] = pv.z; Ps[r * 33 + c4 + 3] = pv.w;
        }
        #pragma unroll
        for (int x = tid; x < 512; x += 256) {
            int r = x >> 4, c4 = (x & 15) << 2;
            float4 vv = *reinterpret_cast<const float4*>(&Vg[(size_t)(j0 + r) * DH + c4]);
            Vs[r * 64 + c4 + 0] = vv.x; Vs[r * 64 + c4 + 1] = vv.y;
            Vs[r * 64 + c4 + 2] = vv.z; Vs[r * 64 + c4 + 3] = vv.w;
        }
        __syncthreads();
        #pragma unroll
        for (int k = 0; k < 32; k++) {
            float vv[4], pv[8];
            #pragma unroll
            for (int c = 0; c < 4; c++) vv[c] = Vs[k * 64 + tx + 16 * c];
            #pragma unroll
            for (int a = 0; a < 8; a++) pv[a] = Ps[(ty + 16 * a) * 33 + k];
            #pragma unroll
            for (int a = 0; a < 8; a++)
                #pragma unroll
                for (int c = 0; c < 4; c++) acc[a][c] += pv[a] * vv[c];
        }
        __syncthreads();
    }

    const int b = bn / NH, n = bn % NH;
    #pragma unroll
    for (int a = 0; a < 8; a++) {
        int i = i0 + ty + 16 * a;
        #pragma unroll
        for (int c = 0; c < 4; c++) {
            int d = tx + 16 * c;
            g_AV[(size_t)(i * BSZ + b) * DM + n * DH + d] = acc[a][c];
        }
    }
}

// ---------------- Kernel 6: output projection GEMM ----------------
// AO[ib][m] = sum_h AV[ib][h] * o_w[m][h]
__global__ __launch_bounds__(256) void out_gemm(const float* __restrict__ OW) {
    __shared__ float As[128][17];
    __shared__ float Bs[128][17];
    const int i0 = blockIdx.y * 128;
    const int j0 = blockIdx.x * 128;
    const int tid = threadIdx.x;
    const int tx = tid & 15, ty = tid >> 4;

    float acc[8][8];
    #pragma unroll
    for (int a = 0; a < 8; a++)
        #pragma unroll
        for (int c = 0; c < 8; c++) acc[a][c] = 0.f;

    for (int kk = 0; kk < DM; kk += 16) {
        #pragma unroll
        for (int x = tid; x < 512; x += 256) {
            int r = x >> 2, c4 = (x & 3) << 2;
            float4 av = *reinterpret_cast<const float4*>(&g_AV[(size_t)(i0 + r) * DM + kk + c4]);
            As[r][c4 + 0] = av.x; As[r][c4 + 1] = av.y;
            As[r][c4 + 2] = av.z; As[r][c4 + 3] = av.w;
            float4 bv = *reinterpret_cast<const float4*>(&OW[(size_t)(j0 + r) * DM + kk + c4]);
            Bs[r][c4 + 0] = bv.x; Bs[r][c4 + 1] = bv.y;
            Bs[r][c4 + 2] = bv.z; Bs[r][c4 + 3] = bv.w;
        }
        __syncthreads();
        #pragma unroll
        for (int k = 0; k < 16; k++) {
            float av[8], bv[8];
            #pragma unroll
            for (int a = 0; a < 8; a++) av[a] = As[ty + 16 * a][k];
            #pragma unroll
            for (int c = 0; c < 8; c++) bv[c] = Bs[tx + 16 * c][k];
            #pragma unroll
            for (int a = 0; a < 8; a++)
                #pragma unroll
                for (int c = 0; c < 8; c++) acc[a][c] += av[a] * bv[c];
        }
        __syncthreads();
    }

    #pragma unroll
    for (int a = 0; a < 8; a++) {
        int ib = i0 + ty + 16 * a;
        #pragma unroll
        for (int c = 0; c < 8; c++) {
            int m = j0 + tx + 16 * c;
            g_AO[(size_t)ib * DM + m] = acc[a][c];
        }
    }
}

// ---------------- Kernel 7: residual + LayerNorm ----------------
__global__ __launch_bounds__(256) void ln_kernel(const float* __restrict__ w,
                                                 const float* __restrict__ gamma,
                                                 const float* __restrict__ beta,
                                                 float* __restrict__ out) {
    const int ib = blockIdx.x;
    const int tid = threadIdx.x;
    const int lane = tid & 31, wrp = tid >> 5;
    __shared__ float redA[8], redB[8];

    float x[3];
    float s = 0.f, ss = 0.f;
    #pragma unroll
    for (int t = 0; t < 3; t++) {
        int m = tid + 256 * t;
        float xv = w[(size_t)ib * DM + m] + g_AO[(size_t)ib * DM + m];
        x[t] = xv;
        s += xv;
        ss += xv * xv;
    }
    #pragma unroll
    for (int st = 16; st > 0; st >>= 1) {
        s += __shfl_xor_sync(0xffffffffu, s, st);
        ss += __shfl_xor_sync(0xffffffffu, ss, st);
    }
    if (lane == 0) { redA[wrp] = s; redB[wrp] = ss; }
    __syncthreads();
    s = 0.f; ss = 0.f;
    #pragma unroll
    for (int t = 0; t < 8; t++) { s += redA[t]; ss += redB[t]; }
    const float mu = s * (1.f / DM);
    const float var = ss * (1.f / DM) - mu * mu;
    const float inv = rsqrtf(var + 1e-5f);
    #pragma unroll
    for (int t = 0; t < 3; t++) {
        int m = tid + 256 * t;
        out[(size_t)ib * DM + m] = (x[t] - mu) * inv * gamma[m] + beta[m];
    }
}

// ---------------- launcher ----------------
extern "C" void kernel_launch(void* const* d_in, const int* in_sizes, int n_in,
                              void* d_out, int out_size) {
    const float* w        = (const float*)d_in[0];
    const float* r_emb    = (const float*)d_in[1];
    const float* r_w_bias = (const float*)d_in[2];
    const float* r_bias   = (const float*)d_in[3];
    const float* qkv_w    = (const float*)d_in[4];
    const float* o_w      = (const float*)d_in[5];
    const float* ln_gamma = (const float*)d_in[6];
    const float* ln_beta  = (const float*)d_in[7];
    float* out = (float*)d_out;

    // score kernel needs >48KB dynamic smem; opt in every call (idempotent, not a stream op)
    const int sc_bytes = SC_SMEM_FLOATS * 4;
    cudaFuncSetAttribute(score_kernel, cudaFuncAttributeMaxDynamicSharedMemorySize, sc_bytes);

    qkv_gemm<<<dim3(2304 / 128, 4096 / 128), 256>>>(w, qkv_w);
    ck_kernel<<<(NBH * QL + 255) / 256, 256>>>(r_w_bias);
    score_kernel<<<dim3(QL / 64, QL / 64, NBH), 256, sc_bytes>>>(r_emb, r_bias);
    softmax_kernel<<<dim3(QL, NBH), 128>>>();
    pv_kernel<<<dim3(QL / 128, NBH), 256>>>();
    out_gemm<<<dim3(DM / 128, 4096 / 128), 256>>>(o_w);
    ln_kernel<<<QL * BSZ, 256>>>(w, ln_gamma, ln_beta, out);
}

// round 9
// speedup vs baseline: 1.1382x; 1.1382x over previous
#include <cuda_runtime.h>
#include <cuda_bf16.h>
#include <math.h>

#define QL 2048
#define BSZ 2
#define NH 12
#define DH 64
#define DM 768
#define NBH (BSZ*NH)   // 24
#define NEG_INF (-1e30f)
#define NTILE 32                 // QL/64 j- and i-tiles
#define NTRI (NTILE*(NTILE+1)/2) // 528 causal tiles per bn

typedef unsigned long long ull;

// packed fp32x2 ops (sm_100+; ptxas never emits FFMA2 from C++, so inline PTX)
#define F2ADD(d, a, b)    asm("add.rn.f32x2 %0, %1, %2;" : "=l"(d) : "l"(a), "l"(b))
#define F2FMA(d, a, b, c) asm("fma.rn.f32x2 %0, %1, %2, %3;" : "=l"(d) : "l"(a), "l"(b), "l"(c))
#define F2PACK1(d, x)     asm("mov.b64 %0, {%1, %1};" : "=l"(d) : "r"(x))

__device__ __forceinline__ float f2lo(ull v) { return __uint_as_float((unsigned)v); }
__device__ __forceinline__ float f2hi(ull v) { return __uint_as_float((unsigned)(v >> 32)); }

// ---------------- static scratch (no runtime allocation allowed) ----------------
__device__ float g_Q[(size_t)NBH*QL*DH];      // [b*NH+n][i][d]
__device__ float g_K[(size_t)NBH*QL*DH];
__device__ float g_V[(size_t)NBH*QL*DH];
__device__ float g_ck[NBH*QL];                // rwb_n . k_j
__device__ float g_S[(size_t)NBH*QL*QL];      // scores / probs (402 MB)
__device__ float g_AV[(size_t)QL*BSZ*DM];     // attn_vec  [ib][h]
__device__ float g_AO[(size_t)QL*BSZ*DM];     // attn_out  [ib][m]

// ---------------- Kernel 1: QKV projection GEMM (FFMA2, B k-major) ----------------
// C[ib][h] = sum_m w[ib][m] * qkv_w[h][m];  ib in [0,4096), h in [0,2304)
// 128x128x16 tiles; 256 threads; 8 rows x (4 col-pairs) microtile.
__global__ __launch_bounds__(256) void qkv_gemm(const float* __restrict__ A,
                                                const float* __restrict__ W) {
    __shared__ float As[128][17];       // [row][k]
    __shared__ float Bst[16][130];      // [k][col], pad to 130
    const int i0 = blockIdx.y * 128;
    const int j0 = blockIdx.x * 128;
    const int tid = threadIdx.x;
    const int tx = tid & 15, ty = tid >> 4;

    ull acc2[8][4];
    #pragma unroll
    for (int a = 0; a < 8; a++)
        #pragma unroll
        for (int c = 0; c < 4; c++) acc2[a][c] = 0ull;

    for (int kk = 0; kk < DM; kk += 16) {
        #pragma unroll
        for (int x = tid; x < 512; x += 256) {
            int r = x >> 2, c4 = (x & 3) << 2;
            float4 av = *reinterpret_cast<const float4*>(&A[(size_t)(i0 + r) * DM + kk + c4]);
            As[r][c4 + 0] = av.x; As[r][c4 + 1] = av.y;
            As[r][c4 + 2] = av.z; As[r][c4 + 3] = av.w;
            float4 bv = *reinterpret_cast<const float4*>(&W[(size_t)(j0 + r) * DM + kk + c4]);
            Bst[c4 + 0][r] = bv.x; Bst[c4 + 1][r] = bv.y;
            Bst[c4 + 2][r] = bv.z; Bst[c4 + 3][r] = bv.w;
        }
        __syncthreads();
        #pragma unroll
        for (int k = 0; k < 16; k++) {
            ull av2[8], bv2[4];
            #pragma unroll
            for (int c = 0; c < 4; c++)
                bv2[c] = *reinterpret_cast<const ull*>(&Bst[k][tx * 2 + 32 * c]);
            #pragma unroll
            for (int a = 0; a < 8; a++) {
                float av = As[ty + 16 * a][k];
                F2PACK1(av2[a], __float_as_uint(av));
            }
            #pragma unroll
            for (int a = 0; a < 8; a++)
                #pragma unroll
                for (int c = 0; c < 4; c++) F2FMA(acc2[a][c], av2[a], bv2[c], acc2[a][c]);
        }
        __syncthreads();
    }

    #pragma unroll
    for (int a = 0; a < 8; a++) {
        int ib = i0 + ty + 16 * a;
        int i = ib >> 1, b = ib & 1;
        #pragma unroll
        for (int c = 0; c < 4; c++) {
            #pragma unroll
            for (int e = 0; e < 2; e++) {
                int h = j0 + tx * 2 + 32 * c + e;
                int which = h / DM;
                int hr = h - which * DM;
                int n = hr >> 6, dd = hr & 63;
                float* dst = (which == 0) ? g_Q : ((which == 1) ? g_K : g_V);
                dst[((size_t)(b * NH + n) * QL + i) * DH + dd] =
                    e ? f2hi(acc2[a][c]) : f2lo(acc2[a][c]);
            }
        }
    }
}

// ---------------- Kernel 2: ck[bn][j] = r_w_bias[n] . K[bn][j] ----------------
__global__ __launch_bounds__(256) void ck_kernel(const float* __restrict__ rwb) {
    int idx = blockIdx.x * 256 + threadIdx.x;
    if (idx >= NBH * QL) return;
    int bn = idx / QL;
    int n = bn % NH;
    const float4* krow = reinterpret_cast<const float4*>(&g_K[(size_t)idx * DH]);
    const float4* wv = reinterpret_cast<const float4*>(&rwb[n * DH]);
    float s = 0.f;
    #pragma unroll
    for (int d = 0; d < DH / 4; d++) {
        float4 kv = krow[d], wvv = wv[d];
        s += kv.x * wvv.x + kv.y * wvv.y + kv.z * wvv.z + kv.w * wvv.w;
    }
    g_ck[idx] = s;
}

// ---------------- Kernel 3: fused causal score (FFMA2, triangular grid) ----------------
// S[i][j] = (q_i.k_j + q_i.rr[i-j] + ck[j] + rb2[i-j]) * SCALE   for j<=i
// rr[d] = r_emb[QL-1-d][n],  rb2[d] = r_bias[QL-1-d][n]
// blockIdx.x = triangular tile id (528 per bn), blockIdx.y = bn.
// 64x64 tile, 256 threads, 4x4 microtile; 127-row rel band; pitch 66 (even -> 8B pairs).
#define SCP 66
#define SC_SMEM_FLOATS (64*SCP + 64*SCP + 127*SCP + 128 + 64)
__global__ __launch_bounds__(256) void score_kernel(const float* __restrict__ r_emb,
                                                    const float* __restrict__ r_bias) {
    const int t = blockIdx.x, bn = blockIdx.y;
    // invert triangular index: it = largest v with v(v+1)/2 <= t
    int it = (int)((sqrtf(8.f * (float)t + 1.f) - 1.f) * 0.5f);
    while ((it + 1) * (it + 2) / 2 <= t) it++;
    while (it * (it + 1) / 2 > t) it--;
    const int jt = t - it * (it + 1) / 2;

    extern __shared__ float sm[];
    float* Qs = sm;                     // 64*SCP
    float* Ks = Qs + 64 * SCP;          // 64*SCP
    float* Rs = Ks + 64 * SCP;          // 127*SCP
    float* Rb = Rs + 127 * SCP;         // 128
    float* ckv = Rb + 128;              // 64

    const int n = bn % NH;
    const int i0 = it * 64, j0 = jt * 64;
    const int dmin = i0 - j0 - 63;
    const int tid = threadIdx.x;

    const float* Qg = g_Q + (size_t)bn * QL * DH;
    const float* Kg = g_K + (size_t)bn * QL * DH;

    #pragma unroll
    for (int x = tid; x < 1024; x += 256) {
        int r = x >> 4, c4 = (x & 15) << 2;
        float4 qv = *reinterpret_cast<const float4*>(&Qg[(size_t)(i0 + r) * DH + c4]);
        *reinterpret_cast<float2*>(&Qs[r * SCP + c4])     = make_float2(qv.x, qv.y);
        *reinterpret_cast<float2*>(&Qs[r * SCP + c4 + 2]) = make_float2(qv.z, qv.w);
        float4 kv = *reinterpret_cast<const float4*>(&Kg[(size_t)(j0 + r) * DH + c4]);
        *reinterpret_cast<float2*>(&Ks[r * SCP + c4])     = make_float2(kv.x, kv.y);
        *reinterpret_cast<float2*>(&Ks[r * SCP + c4 + 2]) = make_float2(kv.z, kv.w);
    }
    for (int x = tid; x < 2032; x += 256) {
        int r = x >> 4, c4 = (x & 15) << 2;
        int d = dmin + r;
        float4 rv = make_float4(0.f, 0.f, 0.f, 0.f);
        if (d >= 0)
            rv = *reinterpret_cast<const float4*>(
                &r_emb[(size_t)(QL - 1 - d) * (NH * DH) + n * DH + c4]);
        *reinterpret_cast<float2*>(&Rs[r * SCP + c4])     = make_float2(rv.x, rv.y);
        *reinterpret_cast<float2*>(&Rs[r * SCP + c4 + 2]) = make_float2(rv.z, rv.w);
    }
    if (tid < 127) {
        int d = dmin + tid;
        Rb[tid] = (d >= 0) ? r_bias[(QL - 1 - d) * NH + n] : 0.f;
    }
    if (tid < 64) ckv[tid] = g_ck[bn * QL + j0 + tid];
    __syncthreads();

    const int tx = tid & 15, ty = tid >> 4;
    // rel row for cell (a,c): 63 + (ty-tx) + 16*(a-c) = (15+ty-tx) + 16*g, g=a-c+3 in [0,7)
    const int rrow0 = 15 + ty - tx;

    ull acc2[4][4];
    #pragma unroll
    for (int a = 0; a < 4; a++)
        #pragma unroll
        for (int c = 0; c < 4; c++) acc2[a][c] = 0ull;

    #pragma unroll 4
    for (int kp = 0; kp < 32; kp++) {
        const int k = kp * 2;
        ull qv2[4], kv2[4], rv2[7];
        #pragma unroll
        for (int a = 0; a < 4; a++)
            qv2[a] = *reinterpret_cast<const ull*>(&Qs[(ty + 16 * a) * SCP + k]);
        #pragma unroll
        for (int c = 0; c < 4; c++)
            kv2[c] = *reinterpret_cast<const ull*>(&Ks[(tx + 16 * c) * SCP + k]);
        #pragma unroll
        for (int g = 0; g < 7; g++)
            rv2[g] = *reinterpret_cast<const ull*>(&Rs[(rrow0 + 16 * g) * SCP + k]);
        #pragma unroll
        for (int a = 0; a < 4; a++)
            #pragma unroll
            for (int c = 0; c < 4; c++) {
                ull kr2;
                F2ADD(kr2, kv2[c], rv2[a - c + 3]);
                F2FMA(acc2[a][c], qv2[a], kr2, acc2[a][c]);
            }
    }

    float* Srow = g_S + (size_t)bn * QL * QL;
    #pragma unroll
    for (int a = 0; a < 4; a++) {
        int i = i0 + ty + 16 * a;
        #pragma unroll
        for (int c = 0; c < 4; c++) {
            int j = j0 + tx + 16 * c;
            float s;
            if (j > i) {
                s = NEG_INF;
            } else {
                float accv = f2lo(acc2[a][c]) + f2hi(acc2[a][c]);
                s = (accv + ckv[tx + 16 * c] + Rb[63 + ty + 16 * a - tx - 16 * c]) * 0.125f;
            }
            Srow[(size_t)i * QL + j] = s;
        }
    }
}

// ---------------- Kernel 4: causal row softmax (float4 I/O, shuffle reduce) ----------------
__global__ __launch_bounds__(128) void softmax_kernel() {
    const int i = blockIdx.x, bn = blockIdx.y;
    float* row = g_S + (size_t)bn * QL * QL + (size_t)i * QL;
    const int len = i + 1;
    const int len4 = len >> 2;          // number of full float4 quads
    const int rem = len & 3;            // scalar tail elements
    const int tid = threadIdx.x;
    const int lane = tid & 31, wrp = tid >> 5;
    __shared__ float red[4];

    float4 v[4];
    int cnt = 0;
    float m = NEG_INF;
    for (int q = tid; q < len4; q += 128) {
        float4 t = reinterpret_cast<const float4*>(row)[q];
        v[cnt++] = t;
        m = fmaxf(m, fmaxf(fmaxf(t.x, t.y), fmaxf(t.z, t.w)));
    }
    float tv = NEG_INF;
    if (tid < rem) tv = row[len4 * 4 + tid];
    m = fmaxf(m, tv);
    #pragma unroll
    for (int s = 16; s > 0; s >>= 1) m = fmaxf(m, __shfl_xor_sync(0xffffffffu, m, s));
    if (lane == 0) red[wrp] = m;
    __syncthreads();
    m = fmaxf(fmaxf(red[0], red[1]), fmaxf(red[2], red[3]));

    float sum = 0.f;
    for (int x = 0; x < cnt; x++) {
        v[x].x = __expf(v[x].x - m);
        v[x].y = __expf(v[x].y - m);
        v[x].z = __expf(v[x].z - m);
        v[x].w = __expf(v[x].w - m);
        sum += (v[x].x + v[x].y) + (v[x].z + v[x].w);
    }
    if (tid < rem) { tv = __expf(tv - m); sum += tv; }
    #pragma unroll
    for (int s = 16; s > 0; s >>= 1) sum += __shfl_xor_sync(0xffffffffu, sum, s);
    __syncthreads();
    if (lane == 0) red[wrp] = sum;
    __syncthreads();
    const float inv = 1.f / (red[0] + red[1] + red[2] + red[3]);

    cnt = 0;
    for (int q = tid; q < len4; q += 128) {
        float4 t = v[cnt++];
        t.x *= inv; t.y *= inv; t.z *= inv; t.w *= inv;
        reinterpret_cast<float4*>(row)[q] = t;
    }
    if (tid < rem) row[len4 * 4 + tid] = tv * inv;
    // zero tail up to this row's 128-aligned PV block boundary
    int jend = ((i >> 7) + 1) << 7;
    if (jend > QL) jend = QL;
    for (int j = len + tid; j < jend; j += 128) row[j] = 0.f;
}

// ---------------- Kernel 5: PV GEMM (FFMA2, V transposed, causal-skipped) ----------------
// AV[i][b][n*64+d] = sum_j P[i][j] * V[j][d];  BM=128, BK=32, 8x4 microtile
__global__ __launch_bounds__(256) void pv_kernel() {
    __shared__ float Ps[128 * 34];      // [i][k] pitch 34 (even)
    __shared__ float Vst[64][34];       // [d][k] transposed, pitch 34
    const int iblk = blockIdx.x, bn = blockIdx.y;
    const int i0 = iblk * 128;
    const float* Pm = g_S + (size_t)bn * QL * QL;
    const float* Vg = g_V + (size_t)bn * QL * DH;
    const int tid = threadIdx.x, tx = tid & 15, ty = tid >> 4;

    ull acc2[8][4];
    #pragma unroll
    for (int a = 0; a < 8; a++)
        #pragma unroll
        for (int c = 0; c < 4; c++) acc2[a][c] = 0ull;

    const int jlim = (i0 + 128 < QL) ? (i0 + 128) : QL;
    for (int j0 = 0; j0 < jlim; j0 += 32) {
        #pragma unroll
        for (int x = tid; x < 1024; x += 256) {
            int r = x >> 3, c4 = (x & 7) << 2;
            float4 pv = *reinterpret_cast<const float4*>(&Pm[(size_t)(i0 + r) * QL + j0 + c4]);
            *reinterpret_cast<float2*>(&Ps[r * 34 + c4])     = make_float2(pv.x, pv.y);
            *reinterpret_cast<float2*>(&Ps[r * 34 + c4 + 2]) = make_float2(pv.z, pv.w);
        }
        #pragma unroll
        for (int x = tid; x < 512; x += 256) {
            int r = x >> 4, c4 = (x & 15) << 2;      // r = k (0..31), c4 = d
            float4 vv = *reinterpret_cast<const float4*>(&Vg[(size_t)(j0 + r) * DH + c4]);
            Vst[c4 + 0][r] = vv.x; Vst[c4 + 1][r] = vv.y;
            Vst[c4 + 2][r] = vv.z; Vst[c4 + 3][r] = vv.w;
        }
        __syncthreads();
        #pragma unroll
        for (int kp = 0; kp < 16; kp++) {
            const int k = kp * 2;
            ull vv2[4], pv2[8];
            #pragma unroll
            for (int c = 0; c < 4; c++)
                vv2[c] = *reinterpret_cast<const ull*>(&Vst[tx + 16 * c][k]);
            #pragma unroll
            for (int a = 0; a < 8; a++)
                pv2[a] = *reinterpret_cast<const ull*>(&Ps[(ty + 16 * a) * 34 + k]);
            #pragma unroll
            for (int a = 0; a < 8; a++)
                #pragma unroll
                for (int c = 0; c < 4; c++) F2FMA(acc2[a][c], pv2[a], vv2[c], acc2[a][c]);
        }
        __syncthreads();
    }

    const int b = bn / NH, n = bn % NH;
    #pragma unroll
    for (int a = 0; a < 8; a++) {
        int i = i0 + ty + 16 * a;
        #pragma unroll
        for (int c = 0; c < 4; c++) {
            int d = tx + 16 * c;
            g_AV[(size_t)(i * BSZ + b) * DM + n * DH + d] = f2lo(acc2[a][c]) + f2hi(acc2[a][c]);
        }
    }
}

// ---------------- Kernel 6: output projection GEMM (FFMA2, B k-major) ----------------
// AO[ib][m] = sum_h AV[ib][h] * o_w[m][h]
__global__ __launch_bounds__(256) void out_gemm(const float* __restrict__ OW) {
    __shared__ float As[128][17];
    __shared__ float Bst[16][130];
    const int i0 = blockIdx.y * 128;
    const int j0 = blockIdx.x * 128;
    const int tid = threadIdx.x;
    const int tx = tid & 15, ty = tid >> 4;

    ull acc2[8][4];
    #pragma unroll
    for (int a = 0; a < 8; a++)
        #pragma unroll
        for (int c = 0; c < 4; c++) acc2[a][c] = 0ull;

    for (int kk = 0; kk < DM; kk += 16) {
        #pragma unroll
        for (int x = tid; x < 512; x += 256) {
            int r = x >> 2, c4 = (x & 3) << 2;
            float4 av = *reinterpret_cast<const float4*>(&g_AV[(size_t)(i0 + r) * DM + kk + c4]);
            As[r][c4 + 0] = av.x; As[r][c4 + 1] = av.y;
            As[r][c4 + 2] = av.z; As[r][c4 + 3] = av.w;
            float4 bv = *reinterpret_cast<const float4*>(&OW[(size_t)(j0 + r) * DM + kk + c4]);
            Bst[c4 + 0][r] = bv.x; Bst[c4 + 1][r] = bv.y;
            Bst[c4 + 2][r] = bv.z; Bst[c4 + 3][r] = bv.w;
        }
        __syncthreads();
        #pragma unroll
        for (int k = 0; k < 16; k++) {
            ull av2[8], bv2[4];
            #pragma unroll
            for (int c = 0; c < 4; c++)
                bv2[c] = *reinterpret_cast<const ull*>(&Bst[k][tx * 2 + 32 * c]);
            #pragma unroll
            for (int a = 0; a < 8; a++) {
                float av = As[ty + 16 * a][k];
                F2PACK1(av2[a], __float_as_uint(av));
            }
            #pragma unroll
            for (int a = 0; a < 8; a++)
                #pragma unroll
                for (int c = 0; c < 4; c++) F2FMA(acc2[a][c], av2[a], bv2[c], acc2[a][c]);
        }
        __syncthreads();
    }

    #pragma unroll
    for (int a = 0; a < 8; a++) {
        int ib = i0 + ty + 16 * a;
        #pragma unroll
        for (int c = 0; c < 4; c++) {
            int m = j0 + tx * 2 + 32 * c;
            g_AO[(size_t)ib * DM + m]     = f2lo(acc2[a][c]);
            g_AO[(size_t)ib * DM + m + 1] = f2hi(acc2[a][c]);
        }
    }
}

// ---------------- Kernel 7: residual + LayerNorm ----------------
__global__ __launch_bounds__(256) void ln_kernel(const float* __restrict__ w,
                                                 const float* __restrict__ gamma,
                                                 const float* __restrict__ beta,
                                                 float* __restrict__ out) {
    const int ib = blockIdx.x;
    const int tid = threadIdx.x;
    const int lane = tid & 31, wrp = tid >> 5;
    __shared__ float redA[8], redB[8];

    float x[3];
    float s = 0.f, ss = 0.f;
    #pragma unroll
    for (int t = 0; t < 3; t++) {
        int m = tid + 256 * t;
        float xv = w[(size_t)ib * DM + m] + g_AO[(size_t)ib * DM + m];
        x[t] = xv;
        s += xv;
        ss += xv * xv;
    }
    #pragma unroll
    for (int st = 16; st > 0; st >>= 1) {
        s += __shfl_xor_sync(0xffffffffu, s, st);
        ss += __shfl_xor_sync(0xffffffffu, ss, st);
    }
    if (lane == 0) { redA[wrp] = s; redB[wrp] = ss; }
    __syncthreads();
    s = 0.f; ss = 0.f;
    #pragma unroll
    for (int t = 0; t < 8; t++) { s += redA[t]; ss += redB[t]; }
    const float mu = s * (1.f / DM);
    const float var = ss * (1.f / DM) - mu * mu;
    const float inv = rsqrtf(var + 1e-5f);
    #pragma unroll
    for (int t = 0; t < 3; t++) {
        int m = tid + 256 * t;
        out[(size_t)ib * DM + m] = (x[t] - mu) * inv * gamma[m] + beta[m];
    }
}

// ---------------- launcher ----------------
extern "C" void kernel_launch(void* const* d_in, const int* in_sizes, int n_in,
                              void* d_out, int out_size) {
    const float* w        = (const float*)d_in[0];
    const float* r_emb    = (const float*)d_in[1];
    const float* r_w_bias = (const float*)d_in[2];
    const float* r_bias   = (const float*)d_in[3];
    const float* qkv_w    = (const float*)d_in[4];
    const float* o_w      = (const float*)d_in[5];
    const float* ln_gamma = (const float*)d_in[6];
    const float* ln_beta  = (const float*)d_in[7];
    float* out = (float*)d_out;

    const int sc_bytes = SC_SMEM_FLOATS * 4;
    cudaFuncSetAttribute(score_kernel, cudaFuncAttributeMaxDynamicSharedMemorySize, sc_bytes);

    qkv_gemm<<<dim3(2304 / 128, 4096 / 128), 256>>>(w, qkv_w);
    ck_kernel<<<(NBH * QL + 255) / 256, 256>>>(r_w_bias);
    score_kernel<<<dim3(NTRI, NBH), 256, sc_bytes>>>(r_emb, r_bias);
    softmax_kernel<<<dim3(QL, NBH), 128>>>();
    pv_kernel<<<dim3(QL / 128, NBH), 256>>>();
    out_gemm<<<dim3(DM / 128, 4096 / 128), 256>>>(o_w);
    ln_kernel<<<QL * BSZ, 256>>>(w, ln_gamma, ln_beta, out);
}

// round 10
// speedup vs baseline: 1.2113x; 1.0642x over previous
#include <cuda_runtime.h>
#include <cuda_bf16.h>
#include <math.h>

#define QL 2048
#define BSZ 2
#define NH 12
#define DH 64
#define DM 768
#define NBH (BSZ*NH)   // 24
#define NEG_INF (-1e30f)
#define NTILE 32       // QL/64 i-tiles

typedef unsigned long long ull;

// packed fp32x2 ops (sm_100+; inline PTX)
#define F2ADD(d, a, b)    asm("add.rn.f32x2 %0, %1, %2;" : "=l"(d) : "l"(a), "l"(b))
#define F2MUL(d, a, b)    asm("mul.rn.f32x2 %0, %1, %2;" : "=l"(d) : "l"(a), "l"(b))
#define F2FMA(d, a, b, c) asm("fma.rn.f32x2 %0, %1, %2, %3;" : "=l"(d) : "l"(a), "l"(b), "l"(c))
#define F2PACK1(d, x)     asm("mov.b64 %0, {%1, %1};" : "=l"(d) : "r"(x))

__device__ __forceinline__ float f2lo(ull v) { return __uint_as_float((unsigned)v); }
__device__ __forceinline__ float f2hi(ull v) { return __uint_as_float((unsigned)(v >> 32)); }

// ---------------- static scratch (no runtime allocation allowed) ----------------
__device__ float g_Q[(size_t)NBH*QL*DH];      // [b*NH+n][i][d]
__device__ float g_K[(size_t)NBH*QL*DH];
__device__ float g_V[(size_t)NBH*QL*DH];
__device__ float g_ck[NBH*QL];                // rwb_n . k_j
__device__ float g_AV[(size_t)QL*BSZ*DM];     // attn_vec  [ib][h]
__device__ float g_AO[(size_t)QL*BSZ*DM];     // attn_out  [ib][m]

// ---------------- Kernel 1: QKV projection GEMM (FFMA2, B k-major) ----------------
__global__ __launch_bounds__(256) void qkv_gemm(const float* __restrict__ A,
                                                const float* __restrict__ W) {
    __shared__ float As[128][17];       // [row][k]
    __shared__ float Bst[16][130];      // [k][col]
    const int i0 = blockIdx.y * 128;
    const int j0 = blockIdx.x * 128;
    const int tid = threadIdx.x;
    const int tx = tid & 15, ty = tid >> 4;

    ull acc2[8][4];
    #pragma unroll
    for (int a = 0; a < 8; a++)
        #pragma unroll
        for (int c = 0; c < 4; c++) acc2[a][c] = 0ull;

    for (int kk = 0; kk < DM; kk += 16) {
        #pragma unroll
        for (int x = tid; x < 512; x += 256) {
            int r = x >> 2, c4 = (x & 3) << 2;
            float4 av = *reinterpret_cast<const float4*>(&A[(size_t)(i0 + r) * DM + kk + c4]);
            As[r][c4 + 0] = av.x; As[r][c4 + 1] = av.y;
            As[r][c4 + 2] = av.z; As[r][c4 + 3] = av.w;
            float4 bv = *reinterpret_cast<const float4*>(&W[(size_t)(j0 + r) * DM + kk + c4]);
            Bst[c4 + 0][r] = bv.x; Bst[c4 + 1][r] = bv.y;
            Bst[c4 + 2][r] = bv.z; Bst[c4 + 3][r] = bv.w;
        }
        __syncthreads();
        #pragma unroll
        for (int k = 0; k < 16; k++) {
            ull av2[8], bv2[4];
            #pragma unroll
            for (int c = 0; c < 4; c++)
                bv2[c] = *reinterpret_cast<const ull*>(&Bst[k][tx * 2 + 32 * c]);
            #pragma unroll
            for (int a = 0; a < 8; a++) {
                float av = As[ty + 16 * a][k];
                F2PACK1(av2[a], __float_as_uint(av));
            }
            #pragma unroll
            for (int a = 0; a < 8; a++)
                #pragma unroll
                for (int c = 0; c < 4; c++) F2FMA(acc2[a][c], av2[a], bv2[c], acc2[a][c]);
        }
        __syncthreads();
    }

    #pragma unroll
    for (int a = 0; a < 8; a++) {
        int ib = i0 + ty + 16 * a;
        int i = ib >> 1, b = ib & 1;
        #pragma unroll
        for (int c = 0; c < 4; c++) {
            #pragma unroll
            for (int e = 0; e < 2; e++) {
                int h = j0 + tx * 2 + 32 * c + e;
                int which = h / DM;
                int hr = h - which * DM;
                int n = hr >> 6, dd = hr & 63;
                float* dst = (which == 0) ? g_Q : ((which == 1) ? g_K : g_V);
                dst[((size_t)(b * NH + n) * QL + i) * DH + dd] =
                    e ? f2hi(acc2[a][c]) : f2lo(acc2[a][c]);
            }
        }
    }
}

// ---------------- Kernel 2: ck[bn][j] = r_w_bias[n] . K[bn][j] ----------------
__global__ __launch_bounds__(256) void ck_kernel(const float* __restrict__ rwb) {
    int idx = blockIdx.x * 256 + threadIdx.x;
    if (idx >= NBH * QL) return;
    int bn = idx / QL;
    int n = bn % NH;
    const float4* krow = reinterpret_cast<const float4*>(&g_K[(size_t)idx * DH]);
    const float4* wv = reinterpret_cast<const float4*>(&rwb[n * DH]);
    float s = 0.f;
    #pragma unroll
    for (int d = 0; d < DH / 4; d++) {
        float4 kv = krow[d], wvv = wv[d];
        s += kv.x * wvv.x + kv.y * wvv.y + kv.z * wvv.z + kv.w * wvv.w;
    }
    g_ck[idx] = s;
}

// ---------------- Kernel 3: fused flash attention (score+softmax+PV) ----------------
// One CTA = one 64-row i-tile of one bn. Loops jt=0..it with online softmax.
// S[i][j] = (q_i.k_j + q_i.rr[i-j] + ck[j] + rb2[i-j]) * SCALE, causal.
#define FSP 66
#define FL_SMEM_FLOATS (64*FSP /*Q*/ + 64*FSP /*K*/ + 127*FSP /*R*/ + 64*FSP /*P*/ + 64*FSP /*Vt*/ + 128 + 64)
__global__ __launch_bounds__(256, 2) void flash_kernel(const float* __restrict__ r_emb,
                                                       const float* __restrict__ r_bias) {
    const int it = (NTILE - 1) - blockIdx.x;   // longest first
    const int bn = blockIdx.y;
    const int n = bn % NH, b = bn / NH;
    const int i0 = it * 64;
    const int tid = threadIdx.x;
    const int tx = tid & 15, ty = tid >> 4;

    extern __shared__ float sm[];
    float* Qs  = sm;                    // 64*FSP
    float* Ks  = Qs + 64 * FSP;         // 64*FSP
    float* Rs  = Ks + 64 * FSP;         // 127*FSP
    float* Ps  = Rs + 127 * FSP;        // 64*FSP
    float* Vst = Ps + 64 * FSP;         // 64*FSP  [d][j]
    float* Rb  = Vst + 64 * FSP;        // 128
    float* ckv = Rb + 128;              // 64

    const float* Qg = g_Q + (size_t)bn * QL * DH;
    const float* Kg = g_K + (size_t)bn * QL * DH;
    const float* Vg = g_V + (size_t)bn * QL * DH;

    // load Q tile once
    #pragma unroll
    for (int x = tid; x < 1024; x += 256) {
        int r = x >> 4, c4 = (x & 15) << 2;
        float4 qv = *reinterpret_cast<const float4*>(&Qg[(size_t)(i0 + r) * DH + c4]);
        *reinterpret_cast<float2*>(&Qs[r * FSP + c4])     = make_float2(qv.x, qv.y);
        *reinterpret_cast<float2*>(&Qs[r * FSP + c4 + 2]) = make_float2(qv.z, qv.w);
    }

    float mrun[4], lrun[4];
    ull O2[4][4];
    #pragma unroll
    for (int a = 0; a < 4; a++) {
        mrun[a] = NEG_INF; lrun[a] = 0.f;
        #pragma unroll
        for (int c = 0; c < 4; c++) O2[a][c] = 0ull;
    }

    const int rrow0 = 15 + ty - tx;

    for (int jt = 0; jt <= it; jt++) {
        const int j0 = jt * 64;
        const int dmin = i0 - j0 - 63;
        __syncthreads();   // previous PV must be done before overwriting tiles

        // load K tile + V tile (transposed) + rel band + biases
        #pragma unroll
        for (int x = tid; x < 1024; x += 256) {
            int r = x >> 4, c4 = (x & 15) << 2;
            float4 kv = *reinterpret_cast<const float4*>(&Kg[(size_t)(j0 + r) * DH + c4]);
            *reinterpret_cast<float2*>(&Ks[r * FSP + c4])     = make_float2(kv.x, kv.y);
            *reinterpret_cast<float2*>(&Ks[r * FSP + c4 + 2]) = make_float2(kv.z, kv.w);
            float4 vv = *reinterpret_cast<const float4*>(&Vg[(size_t)(j0 + r) * DH + c4]);
            Vst[(c4 + 0) * FSP + r] = vv.x; Vst[(c4 + 1) * FSP + r] = vv.y;
            Vst[(c4 + 2) * FSP + r] = vv.z; Vst[(c4 + 3) * FSP + r] = vv.w;
        }
        for (int x = tid; x < 2032; x += 256) {
            int r = x >> 4, c4 = (x & 15) << 2;
            int d = dmin + r;
            float4 rv = make_float4(0.f, 0.f, 0.f, 0.f);
            if (d >= 0)
                rv = *reinterpret_cast<const float4*>(
                    &r_emb[(size_t)(QL - 1 - d) * (NH * DH) + n * DH + c4]);
            *reinterpret_cast<float2*>(&Rs[r * FSP + c4])     = make_float2(rv.x, rv.y);
            *reinterpret_cast<float2*>(&Rs[r * FSP + c4 + 2]) = make_float2(rv.z, rv.w);
        }
        if (tid < 127) {
            int d = dmin + tid;
            Rb[tid] = (d >= 0) ? r_bias[(QL - 1 - d) * NH + n] : 0.f;
        }
        if (tid < 64) ckv[tid] = g_ck[bn * QL + j0 + tid];
        __syncthreads();

        // ---- score tile (FFMA2 mainloop, identical to proven score_kernel) ----
        ull acc2[4][4];
        #pragma unroll
        for (int a = 0; a < 4; a++)
            #pragma unroll
            for (int c = 0; c < 4; c++) acc2[a][c] = 0ull;

        #pragma unroll 4
        for (int kp = 0; kp < 32; kp++) {
            const int k = kp * 2;
            ull qv2[4], kv2[4], rv2[7];
            #pragma unroll
            for (int a = 0; a < 4; a++)
                qv2[a] = *reinterpret_cast<const ull*>(&Qs[(ty + 16 * a) * FSP + k]);
            #pragma unroll
            for (int c = 0; c < 4; c++)
                kv2[c] = *reinterpret_cast<const ull*>(&Ks[(tx + 16 * c) * FSP + k]);
            #pragma unroll
            for (int g = 0; g < 7; g++)
                rv2[g] = *reinterpret_cast<const ull*>(&Rs[(rrow0 + 16 * g) * FSP + k]);
            #pragma unroll
            for (int a = 0; a < 4; a++)
                #pragma unroll
                for (int c = 0; c < 4; c++) {
                    ull kr2;
                    F2ADD(kr2, kv2[c], rv2[a - c + 3]);
                    F2FMA(acc2[a][c], qv2[a], kr2, acc2[a][c]);
                }
        }

        float s[4][4];
        #pragma unroll
        for (int a = 0; a < 4; a++)
            #pragma unroll
            for (int c = 0; c < 4; c++) {
                float accv = f2lo(acc2[a][c]) + f2hi(acc2[a][c]);
                s[a][c] = (accv + ckv[tx + 16 * c] + Rb[63 + ty + 16 * a - tx - 16 * c]) * 0.125f;
            }
        if (jt == it) {
            #pragma unroll
            for (int a = 0; a < 4; a++)
                #pragma unroll
                for (int c = 0; c < 4; c++)
                    if (tx + 16 * c > ty + 16 * a) s[a][c] = NEG_INF;
        }

        // ---- online softmax update (per-row over 16 tx threads) ----
        #pragma unroll
        for (int a = 0; a < 4; a++) {
            float tm = fmaxf(fmaxf(s[a][0], s[a][1]), fmaxf(s[a][2], s[a][3]));
            #pragma unroll
            for (int w = 8; w > 0; w >>= 1) tm = fmaxf(tm, __shfl_xor_sync(0xffffffffu, tm, w));
            float mn = fmaxf(mrun[a], tm);
            float al = __expf(mrun[a] - mn);
            float ts = 0.f;
            #pragma unroll
            for (int c = 0; c < 4; c++) {
                float p = __expf(s[a][c] - mn);
                s[a][c] = p;
                ts += p;
            }
            #pragma unroll
            for (int w = 8; w > 0; w >>= 1) ts += __shfl_xor_sync(0xffffffffu, ts, w);
            lrun[a] = lrun[a] * al + ts;
            mrun[a] = mn;
            ull al2;
            F2PACK1(al2, __float_as_uint(al));
            #pragma unroll
            for (int c = 0; c < 4; c++) F2MUL(O2[a][c], O2[a][c], al2);
        }

        // ---- P to smem, then PV accumulate ----
        #pragma unroll
        for (int a = 0; a < 4; a++)
            #pragma unroll
            for (int c = 0; c < 4; c++)
                Ps[(ty + 16 * a) * FSP + tx + 16 * c] = s[a][c];
        __syncthreads();

        #pragma unroll 4
        for (int kp = 0; kp < 32; kp++) {
            const int k = kp * 2;
            ull pv2[4], vv2[4];
            #pragma unroll
            for (int a = 0; a < 4; a++)
                pv2[a] = *reinterpret_cast<const ull*>(&Ps[(ty + 16 * a) * FSP + k]);
            #pragma unroll
            for (int c = 0; c < 4; c++)
                vv2[c] = *reinterpret_cast<const ull*>(&Vst[(tx + 16 * c) * FSP + k]);
            #pragma unroll
            for (int a = 0; a < 4; a++)
                #pragma unroll
                for (int c = 0; c < 4; c++) F2FMA(O2[a][c], pv2[a], vv2[c], O2[a][c]);
        }
    }

    // epilogue: normalize and write attn_vec
    #pragma unroll
    for (int a = 0; a < 4; a++) {
        float inv = 1.f / lrun[a];
        int i = i0 + ty + 16 * a;
        #pragma unroll
        for (int c = 0; c < 4; c++) {
            int d = tx + 16 * c;
            g_AV[(size_t)(i * BSZ + b) * DM + n * DH + d] =
                (f2lo(O2[a][c]) + f2hi(O2[a][c])) * inv;
        }
    }
}

// ---------------- Kernel 4: output projection GEMM (FFMA2, B k-major) ----------------
__global__ __launch_bounds__(256) void out_gemm(const float* __restrict__ OW) {
    __shared__ float As[128][17];
    __shared__ float Bst[16][130];
    const int i0 = blockIdx.y * 128;
    const int j0 = blockIdx.x * 128;
    const int tid = threadIdx.x;
    const int tx = tid & 15, ty = tid >> 4;

    ull acc2[8][4];
    #pragma unroll
    for (int a = 0; a < 8; a++)
        #pragma unroll
        for (int c = 0; c < 4; c++) acc2[a][c] = 0ull;

    for (int kk = 0; kk < DM; kk += 16) {
        #pragma unroll
        for (int x = tid; x < 512; x += 256) {
            int r = x >> 2, c4 = (x & 3) << 2;
            float4 av = *reinterpret_cast<const float4*>(&g_AV[(size_t)(i0 + r) * DM + kk + c4]);
            As[r][c4 + 0] = av.x; As[r][c4 + 1] = av.y;
            As[r][c4 + 2] = av.z; As[r][c4 + 3] = av.w;
            float4 bv = *reinterpret_cast<const float4*>(&OW[(size_t)(j0 + r) * DM + kk + c4]);
            Bst[c4 + 0][r] = bv.x; Bst[c4 + 1][r] = bv.y;
            Bst[c4 + 2][r] = bv.z; Bst[c4 + 3][r] = bv.w;
        }
        __syncthreads();
        #pragma unroll
        for (int k = 0; k < 16; k++) {
            ull av2[8], bv2[4];
            #pragma unroll
            for (int c = 0; c < 4; c++)
                bv2[c] = *reinterpret_cast<const ull*>(&Bst[k][tx * 2 + 32 * c]);
            #pragma unroll
            for (int a = 0; a < 8; a++) {
                float av = As[ty + 16 * a][k];
                F2PACK1(av2[a], __float_as_uint(av));
            }
            #pragma unroll
            for (int a = 0; a < 8; a++)
                #pragma unroll
                for (int c = 0; c < 4; c++) F2FMA(acc2[a][c], av2[a], bv2[c], acc2[a][c]);
        }
        __syncthreads();
    }

    #pragma unroll
    for (int a = 0; a < 8; a++) {
        int ib = i0 + ty + 16 * a;
        #pragma unroll
        for (int c = 0; c < 4; c++) {
            int m = j0 + tx * 2 + 32 * c;
            g_AO[(size_t)ib * DM + m]     = f2lo(acc2[a][c]);
            g_AO[(size_t)ib * DM + m + 1] = f2hi(acc2[a][c]);
        }
    }
}

// ---------------- Kernel 5: residual + LayerNorm ----------------
__global__ __launch_bounds__(256) void ln_kernel(const float* __restrict__ w,
                                                 const float* __restrict__ gamma,
                                                 const float* __restrict__ beta,
                                                 float* __restrict__ out) {
    const int ib = blockIdx.x;
    const int tid = threadIdx.x;
    const int lane = tid & 31, wrp = tid >> 5;
    __shared__ float redA[8], redB[8];

    float x[3];
    float s = 0.f, ss = 0.f;
    #pragma unroll
    for (int t = 0; t < 3; t++) {
        int m = tid + 256 * t;
        float xv = w[(size_t)ib * DM + m] + g_AO[(size_t)ib * DM + m];
        x[t] = xv;
        s += xv;
        ss += xv * xv;
    }
    #pragma unroll
    for (int st = 16; st > 0; st >>= 1) {
        s += __shfl_xor_sync(0xffffffffu, s, st);
        ss += __shfl_xor_sync(0xffffffffu, ss, st);
    }
    if (lane == 0) { redA[wrp] = s; redB[wrp] = ss; }
    __syncthreads();
    s = 0.f; ss = 0.f;
    #pragma unroll
    for (int t = 0; t < 8; t++) { s += redA[t]; ss += redB[t]; }
    const float mu = s * (1.f / DM);
    const float var = ss * (1.f / DM) - mu * mu;
    const float inv = rsqrtf(var + 1e-5f);
    #pragma unroll
    for (int t = 0; t < 3; t++) {
        int m = tid + 256 * t;
        out[(size_t)ib * DM + m] = (x[t] - mu) * inv * gamma[m] + beta[m];
    }
}

// ---------------- launcher ----------------
extern "C" void kernel_launch(void* const* d_in, const int* in_sizes, int n_in,
                              void* d_out, int out_size) {
    const float* w        = (const float*)d_in[0];
    const float* r_emb    = (const float*)d_in[1];
    const float* r_w_bias = (const float*)d_in[2];
    const float* r_bias   = (const float*)d_in[3];
    const float* qkv_w    = (const float*)d_in[4];
    const float* o_w      = (const float*)d_in[5];
    const float* ln_gamma = (const float*)d_in[6];
    const float* ln_beta  = (const float*)d_in[7];
    float* out = (float*)d_out;

    const int fl_bytes = FL_SMEM_FLOATS * 4;
    cudaFuncSetAttribute(flash_kernel, cudaFuncAttributeMaxDynamicSharedMemorySize, fl_bytes);

    qkv_gemm<<<dim3(2304 / 128, 4096 / 128), 256>>>(w, qkv_w);
    ck_kernel<<<(NBH * QL + 255) / 256, 256>>>(r_w_bias);
    flash_kernel<<<dim3(NTILE, NBH), 256, fl_bytes>>>(r_emb, r_bias);
    out_gemm<<<dim3(DM / 128, 4096 / 128), 256>>>(o_w);
    ln_kernel<<<QL * BSZ, 256>>>(w, ln_gamma, ln_beta, out);
}